// round 3
// baseline (speedup 1.0000x reference)
#include <cuda_runtime.h>
#include <math.h>

typedef unsigned long long ull;

// Problem constants
#define N_      16
#define C_      128
#define S_      16384
#define K_      64

#define SP      64                  // positions per sub-tile
#define NSUBT   (S_ / SP)           // 256 sub-tiles per n
#define CHUNKS  37                  // blocks per n (592 total = 2 waves x 296 @ occ 2)
#define NBLOCKS (N_ * CHUNKS)       // 592
#define THREADS 256

// Deterministic scratch (allocations forbidden): per-block partials.
__device__ float g_part[(size_t)NBLOCKS * K_ * C_];   // 19.4 MB
__device__ float g_apart[NBLOCKS * K_];

// smem layout (floats)
#define XT_STRIDE 130               // [SP][130] : conflict-tuned row stride
#define SM_XT   0
#define SM_WS   (SM_XT + SP * XT_STRIDE)       // [K_][C_]
#define SM_LG   (SM_WS + K_ * C_)              // [K_][SP+1]
#define SM_BSH  (SM_LG + K_ * (SP + 1))        // [K_]
#define SM_FLTS (SM_BSH + K_)
#define MAIN_SMEM_BYTES (SM_FLTS * sizeof(float))

// ---- Blackwell packed fp32x2 helpers ----
__device__ __forceinline__ ull pk2(float x, float y) {
    ull r; asm("mov.b64 %0, {%1, %2};" : "=l"(r) : "f"(x), "f"(y)); return r;
}
__device__ __forceinline__ float2 upk2(ull v) {
    float2 r; asm("mov.b64 {%0, %1}, %2;" : "=f"(r.x), "=f"(r.y) : "l"(v)); return r;
}
__device__ __forceinline__ ull fma2(ull a, ull b, ull c) {
    ull d; asm("fma.rn.f32x2 %0, %1, %2, %3;" : "=l"(d) : "l"(a), "l"(b), "l"(c)); return d;
}

__global__ __launch_bounds__(THREADS, 2)
void netvlad_main_kernel(const float* __restrict__ x,
                         const float* __restrict__ fc_w,
                         const float* __restrict__ fc_b)
{
    extern __shared__ float sm[];
    float* xt  = sm + SM_XT;    // [SP][130]  x tile, transposed (sp-major)
    float* Ws  = sm + SM_WS;    // [K_][C_]
    float* lg  = sm + SM_LG;    // [K_][SP+1] logits -> softmax (scaled in place)
    float* bsh = sm + SM_BSH;   // [K_]

    const int t  = threadIdx.x;
    const int n  = blockIdx.x / CHUNKS;
    const int ci = blockIdx.x % CHUNKS;
    const int sub_lo = (ci * NSUBT) / CHUNKS;
    const int sub_hi = ((ci + 1) * NSUBT) / CHUNKS;

    for (int i = t; i < K_ * C_; i += THREADS) Ws[i] = fc_w[i];
    if (t < K_) bsh[t] = fc_b[t];

    const int tk  = t >> 4;    // 0..15 : k-group
    const int ts  = t & 15;    // 0..15 : sp/c-group
    const int spq = t >> 2;    // 0..63 : quad-mapped position
    const int pq  = t & 3;     // 0..3  : quad member

    // persistent packed vlad accumulator: k = 4*tk+i, c-pair cp = ts+16*j
    ull vacc[4][4];
#pragma unroll
    for (int i = 0; i < 4; i++)
#pragma unroll
        for (int j = 0; j < 4; j++) vacc[i][j] = 0ULL;
    float asum_r = 0.0f;       // meaningful only on pq==0 (k = spq)

    const float* xn = x + (size_t)n * C_ * S_;

    for (int sub = sub_lo; sub < sub_hi; sub++) {
        const int s0 = sub * SP;

        __syncthreads();   // guard: prev iter's xt/lg readers done

        // ---- load x tile, transposed into xt[sp][c] ----
#pragma unroll
        for (int r = 0; r < (C_ * SP) / THREADS; r++) {
            int idx = r * THREADS + t;
            int c = idx >> 6, sp = idx & 63;
            xt[sp * XT_STRIDE + c] = xn[(size_t)c * S_ + s0 + sp];
        }
        __syncthreads();

        // ---- per-position L2 normalize (quad of lanes per sp, shuffle reduce) ----
        {
            float2* q = (float2*)(xt + spq * XT_STRIDE + pq * 32);
            ull ssp = 0ULL;
#pragma unroll
            for (int i = 0; i < 16; i++) {
                float2 v = q[i];
                ull up = pk2(v.x, v.y);
                ssp = fma2(up, up, ssp);
            }
            float2 s2 = upk2(ssp);
            float ss = s2.x + s2.y;
            ss += __shfl_xor_sync(0xffffffffu, ss, 1);
            ss += __shfl_xor_sync(0xffffffffu, ss, 2);
            float rin = 1.0f / fmaxf(sqrtf(ss), 1e-12f);
#pragma unroll
            for (int i = 0; i < 16; i++) {
                float2 v = q[i];
                v.x *= rin; v.y *= rin;
                q[i] = v;
            }
        }
        __syncthreads();

        // ---- GEMM1: lg[k][sp] = sum_c W[k][c]*xt[sp][c] + b[k]  (packed over c) ----
        {
            ull acc[4][4];
#pragma unroll
            for (int i = 0; i < 4; i++)
#pragma unroll
                for (int j = 0; j < 4; j++) acc[i][j] = 0ULL;

#pragma unroll 2
            for (int cp = 0; cp < C_ / 2; cp++) {
                ull wp[4], xp[4];
#pragma unroll
                for (int i = 0; i < 4; i++) {
                    float2 v = *(const float2*)(Ws + (4 * tk + i) * C_ + 2 * cp);
                    wp[i] = pk2(v.x, v.y);
                }
#pragma unroll
                for (int j = 0; j < 4; j++) {
                    float2 v = *(const float2*)(xt + (ts + 16 * j) * XT_STRIDE + 2 * cp);
                    xp[j] = pk2(v.x, v.y);
                }
#pragma unroll
                for (int i = 0; i < 4; i++)
#pragma unroll
                    for (int j = 0; j < 4; j++)
                        acc[i][j] = fma2(wp[i], xp[j], acc[i][j]);
            }
#pragma unroll
            for (int i = 0; i < 4; i++) {
                float bb = bsh[4 * tk + i];
#pragma unroll
                for (int j = 0; j < 4; j++) {
                    float2 a = upk2(acc[i][j]);
                    lg[(4 * tk + i) * (SP + 1) + ts + 16 * j] = a.x + a.y + bb;
                }
            }
        }
        __syncthreads();

        // ---- softmax over K per position (quad of lanes per sp, shuffle reduce) ----
        {
            float m = -1e30f;
#pragma unroll
            for (int kk = 0; kk < 16; kk++)
                m = fmaxf(m, lg[(16 * pq + kk) * (SP + 1) + spq]);
            m = fmaxf(m, __shfl_xor_sync(0xffffffffu, m, 1));
            m = fmaxf(m, __shfl_xor_sync(0xffffffffu, m, 2));
            float s = 0.0f;
#pragma unroll
            for (int kk = 0; kk < 16; kk++) {
                float e = __expf(lg[(16 * pq + kk) * (SP + 1) + spq] - m);
                lg[(16 * pq + kk) * (SP + 1) + spq] = e;
                s += e;
            }
            s += __shfl_xor_sync(0xffffffffu, s, 1);
            s += __shfl_xor_sync(0xffffffffu, s, 2);
            float rs = 1.0f / s;
#pragma unroll
            for (int kk = 0; kk < 16; kk++)
                lg[(16 * pq + kk) * (SP + 1) + spq] *= rs;
        }
        __syncthreads();

        // ---- a_sum partials: k = spq, quad splits sp range, shuffle reduce ----
        {
            float s = 0.0f;
#pragma unroll
            for (int i = 0; i < 16; i++)
                s += lg[spq * (SP + 1) + 16 * pq + i];
            s += __shfl_xor_sync(0xffffffffu, s, 1);
            s += __shfl_xor_sync(0xffffffffu, s, 2);
            if (pq == 0) asum_r += s;
        }

        // ---- GEMM2: vacc[k][2cp..2cp+1] += soft[k][sp] * xt[sp][2cp..]  (packed over c) ----
#pragma unroll 1
        for (int sp = 0; sp < SP; sp++) {
            ull svp[4], xp[4];
#pragma unroll
            for (int i = 0; i < 4; i++) {
                float sv = lg[(4 * tk + i) * (SP + 1) + sp];
                svp[i] = pk2(sv, sv);
            }
#pragma unroll
            for (int j = 0; j < 4; j++) {
                float2 v = *(const float2*)(xt + sp * XT_STRIDE + 2 * (ts + 16 * j));
                xp[j] = pk2(v.x, v.y);
            }
#pragma unroll
            for (int i = 0; i < 4; i++)
#pragma unroll
                for (int j = 0; j < 4; j++)
                    vacc[i][j] = fma2(svp[i], xp[j], vacc[i][j]);
        }
    }

    // ---- deterministic per-block partial writes (64-bit stores) ----
    float* vb = g_part + (size_t)blockIdx.x * (K_ * C_);
#pragma unroll
    for (int i = 0; i < 4; i++)
#pragma unroll
        for (int j = 0; j < 4; j++) {
            float2 a = upk2(vacc[i][j]);
            *(float2*)(vb + (4 * tk + i) * C_ + 2 * (ts + 16 * j)) = a;
        }
    if (pq == 0) g_apart[blockIdx.x * K_ + spq] = asum_r;
}

// F1: one block per (k, n): reduce 37 chunk partials, subtract a_sum*centroid,
// intra-normalize the row, write normalized row into chunk-0 slot + ssq scalar.
__global__ __launch_bounds__(128)
void netvlad_reduce_kernel(const float* __restrict__ centroids)
{
    __shared__ float asv[CHUNKS];
    __shared__ float wred[4];

    const int k = blockIdx.x;
    const int n = blockIdx.y;
    const int c = threadIdx.x;

    if (c < CHUNKS) asv[c] = g_apart[(n * CHUNKS + c) * K_ + k];
    __syncthreads();
    float a = 0.0f;
#pragma unroll
    for (int ch = 0; ch < CHUNKS; ch++) a += asv[ch];

    float s = 0.0f;
#pragma unroll 4
    for (int ch = 0; ch < CHUNKS; ch++)
        s += g_part[(size_t)(n * CHUNKS + ch) * (K_ * C_) + k * C_ + c];

    float val = s - a * centroids[k * C_ + c];

    float ss = val * val;
#pragma unroll
    for (int off = 16; off; off >>= 1) ss += __shfl_xor_sync(0xffffffffu, ss, off);
    if ((c & 31) == 0) wred[c >> 5] = ss;
    __syncthreads();
    float tot = wred[0] + wred[1] + wred[2] + wred[3];
    float rn = 1.0f / fmaxf(sqrtf(tot), 1e-12f);

    g_part[(size_t)(n * CHUNKS) * (K_ * C_) + k * C_ + c] = val * rn;
    if (c == 0) g_apart[(n * CHUNKS) * K_ + k] = tot * rn * rn;  // ||row||^2 after norm
}

// F2: per n, global L2 normalize the 8192-dim vector.
__global__ __launch_bounds__(256)
void netvlad_final_kernel(float* __restrict__ out)
{
    __shared__ float kss[K_];
    __shared__ float rs_sh;

    const int n = blockIdx.x;
    const int t = threadIdx.x;

    if (t < K_) kss[t] = g_apart[(n * CHUNKS) * K_ + t];
    __syncthreads();
    if (t == 0) {
        float tot = 0.0f;
#pragma unroll
        for (int k = 0; k < K_; k++) tot += kss[k];
        rs_sh = 1.0f / fmaxf(sqrtf(tot), 1e-12f);
    }
    __syncthreads();
    const float rsc = rs_sh;

    const float* src = g_part + (size_t)(n * CHUNKS) * (K_ * C_);
#pragma unroll 4
    for (int i = t; i < K_ * C_; i += 256)
        out[(size_t)n * K_ * C_ + i] = src[i] * rsc;
}

extern "C" void kernel_launch(void* const* d_in, const int* in_sizes, int n_in,
                              void* d_out, int out_size)
{
    const float* x    = (const float*)d_in[0];   // [16,128,16384]
    const float* fc_w = (const float*)d_in[1];   // [64,128]
    const float* fc_b = (const float*)d_in[2];   // [64]
    const float* cent = (const float*)d_in[3];   // [64,128]
    float* out = (float*)d_out;                  // [16, 8192] fp32

    cudaFuncSetAttribute(netvlad_main_kernel,
                         cudaFuncAttributeMaxDynamicSharedMemorySize,
                         (int)MAIN_SMEM_BYTES);

    netvlad_main_kernel<<<NBLOCKS, THREADS, MAIN_SMEM_BYTES>>>(x, fc_w, fc_b);
    netvlad_reduce_kernel<<<dim3(K_, N_), 128>>>(cent);
    netvlad_final_kernel<<<N_, 256>>>(out);
}

// round 4
// speedup vs baseline: 1.3329x; 1.3329x over previous
#include <cuda_runtime.h>
#include <math.h>

typedef unsigned long long ull;

// Problem constants
#define N_      16
#define C_      128
#define S_      16384
#define K_      64

#define SP      64
#define NSUBT   (S_ / SP)           // 256 sub-tiles per n
#define CHUNKS  37                  // 592 blocks = 2 waves x 296 @ occ 2
#define NBLOCKS (N_ * CHUNKS)
#define THREADS 256

// Deterministic scratch (allocations forbidden)
__device__ float g_part[(size_t)NBLOCKS * K_ * C_];
__device__ float g_apart[NBLOCKS * K_];

// smem strides (floats) — all rows 16B-aligned, conflict-tuned
#define P_XT 132
#define P_W  132
#define P_LG 68

#define SM_XT   0
#define SM_WS   (SM_XT + SP * P_XT)       // x tile [sp][c], RAW (unnormalized)
#define SM_LG   (SM_WS + K_ * P_W)        // logits/soft [sp][k]
#define SM_PART (SM_LG + SP * P_LG)       // ssq partials [4][64]
#define SM_RIN  (SM_PART + 256)           // 1/max(||x||,eps) per sp
#define SM_NRM  (SM_RIN + 64)             // max(||x||,eps) per sp
#define SM_BSH  (SM_NRM + 64)
#define SM_FLTS (SM_BSH + 64)
#define MAIN_SMEM_BYTES (SM_FLTS * sizeof(float))   // ~86.9 KB -> occ 2

__device__ __forceinline__ ull pk2(float x, float y) {
    ull r; asm("mov.b64 %0, {%1, %2};" : "=l"(r) : "f"(x), "f"(y)); return r;
}
__device__ __forceinline__ float2 upk2(ull v) {
    float2 r; asm("mov.b64 {%0, %1}, %2;" : "=f"(r.x), "=f"(r.y) : "l"(v)); return r;
}
__device__ __forceinline__ ull fma2(ull a, ull b, ull c) {
    ull d; asm("fma.rn.f32x2 %0, %1, %2, %3;" : "=l"(d) : "l"(a), "l"(b), "l"(c)); return d;
}

__global__ __launch_bounds__(THREADS, 2)
void netvlad_main_kernel(const float* __restrict__ x,
                         const float* __restrict__ fc_w,
                         const float* __restrict__ fc_b)
{
    extern __shared__ float sm[];
    float* xt    = sm + SM_XT;
    float* Ws    = sm + SM_WS;
    float* lg    = sm + SM_LG;
    float* partb = sm + SM_PART;
    float* rin_s = sm + SM_RIN;
    float* nrm_s = sm + SM_NRM;
    float* bsh   = sm + SM_BSH;

    const int t  = threadIdx.x;
    const int n  = blockIdx.x / CHUNKS;
    const int ci = blockIdx.x % CHUNKS;
    const int sub_lo = (ci * NSUBT) / CHUNKS;
    const int sub_hi = ((ci + 1) * NSUBT) / CHUNKS;

    // W with padded stride 132 (keeps broadcast wp loads in distinct bank quads)
    for (int i = t; i < K_ * C_; i += THREADS)
        Ws[(i >> 7) * P_W + (i & 127)] = fc_w[i];
    if (t < K_) bsh[t] = fc_b[t];
    __syncthreads();

    const int tk = t >> 4;              // 0..15 : k-group (k = 4*tk+i)
    const int ts = t & 15;              // 0..15 : GEMM1 sp-group / GEMM2 c-group
    const int sp_l = t & 63;            // load phase: owned position
    const int cg   = t >> 6;            // load phase: channel group 0..3
    const int spm  = 8 * (t >> 5) + (t & 7);   // softmax position
    const int kc   = (t >> 3) & 3;             // softmax k-chunk

    float b_i[4];
#pragma unroll
    for (int i = 0; i < 4; i++) b_i[i] = bsh[4 * tk + i];

    ull vacc[4][4];
#pragma unroll
    for (int i = 0; i < 4; i++)
#pragma unroll
        for (int j = 0; j < 4; j++) vacc[i][j] = 0ULL;
    float asum_r = 0.0f;                // valid on t < 64 (k = t)

    const float* xn = x + (size_t)n * C_ * S_;
    const float* wrow  = Ws + (4 * tk) * P_W;
    const float* xrow1 = xt + ts * P_XT;          // GEMM1 operand rows
    const float* xcol2 = xt + 4 * ts;             // GEMM2 c-chunks
    const float* lrow  = lg + spm * P_LG + 16 * kc;

    for (int sub = sub_lo; sub < sub_hi; sub++) {
        const int s0 = sub * SP;

        __syncthreads();   // xt/lg readers of previous sub-tile done

        // ---- load RAW x tile (transposed) + ssq on the fly ----
        {
            float ssq = 0.0f;
#pragma unroll
            for (int r = 0; r < 8; r++) {
                const int cb = 16 * r + 4 * cg;
                float v0 = xn[(size_t)(cb + 0) * S_ + s0 + sp_l];
                float v1 = xn[(size_t)(cb + 1) * S_ + s0 + sp_l];
                float v2 = xn[(size_t)(cb + 2) * S_ + s0 + sp_l];
                float v3 = xn[(size_t)(cb + 3) * S_ + s0 + sp_l];
                ssq += v0 * v0 + v1 * v1 + v2 * v2 + v3 * v3;
                float4 q = make_float4(v0, v1, v2, v3);
                *(float4*)(xt + sp_l * P_XT + cb) = q;   // conflict-free phases
            }
            partb[cg * 64 + sp_l] = ssq;
        }
        __syncthreads();

        if (t < SP) {
            float ss = partb[t] + partb[64 + t] + partb[128 + t] + partb[192 + t];
            float nm = fmaxf(sqrtf(ss), 1e-12f);
            nrm_s[t] = nm;
            rin_s[t] = 1.0f / nm;
        }
        __syncthreads();

        // ---- GEMM1: lg[sp][k] = (sum_c W[k][c]*xraw[sp][c]) * rin[sp] + b[k] ----
        {
            ull acc[4][4];
#pragma unroll
            for (int i = 0; i < 4; i++)
#pragma unroll
                for (int j = 0; j < 4; j++) acc[i][j] = 0ULL;

#pragma unroll 8
            for (int st = 0; st < 32; st++) {
                ulonglong2 wv[4], xv[4];
#pragma unroll
                for (int i = 0; i < 4; i++)
                    wv[i] = *(const ulonglong2*)(wrow + i * P_W + 4 * st);
#pragma unroll
                for (int j = 0; j < 4; j++)
                    xv[j] = *(const ulonglong2*)(xrow1 + j * 16 * P_XT + 4 * st);
#pragma unroll
                for (int i = 0; i < 4; i++)
#pragma unroll
                    for (int j = 0; j < 4; j++) {
                        acc[i][j] = fma2(wv[i].x, xv[j].x, acc[i][j]);
                        acc[i][j] = fma2(wv[i].y, xv[j].y, acc[i][j]);
                    }
            }
#pragma unroll
            for (int j = 0; j < 4; j++) {
                const int sp = ts + 16 * j;
                const float rj = rin_s[sp];
                float4 o;
                float2 a0 = upk2(acc[0][j]);
                float2 a1 = upk2(acc[1][j]);
                float2 a2 = upk2(acc[2][j]);
                float2 a3 = upk2(acc[3][j]);
                o.x = (a0.x + a0.y) * rj + b_i[0];
                o.y = (a1.x + a1.y) * rj + b_i[1];
                o.z = (a2.x + a2.y) * rj + b_i[2];
                o.w = (a3.x + a3.y) * rj + b_i[3];
                *(float4*)(lg + sp * P_LG + 4 * tk) = o;
            }
        }
        __syncthreads();

        // ---- softmax over K per sp; write soft*rin[sp] (for GEMM2) ----
        {
            float4 v[4];
#pragma unroll
            for (int i = 0; i < 4; i++) v[i] = *(const float4*)(lrow + 4 * i);
            float m = -1e30f;
#pragma unroll
            for (int i = 0; i < 4; i++)
                m = fmaxf(fmaxf(fmaxf(m, v[i].x), fmaxf(v[i].y, v[i].z)), v[i].w);
            m = fmaxf(m, __shfl_xor_sync(0xffffffffu, m, 8));
            m = fmaxf(m, __shfl_xor_sync(0xffffffffu, m, 16));
            float s = 0.0f;
#pragma unroll
            for (int i = 0; i < 4; i++) {
                v[i].x = __expf(v[i].x - m); s += v[i].x;
                v[i].y = __expf(v[i].y - m); s += v[i].y;
                v[i].z = __expf(v[i].z - m); s += v[i].z;
                v[i].w = __expf(v[i].w - m); s += v[i].w;
            }
            s += __shfl_xor_sync(0xffffffffu, s, 8);
            s += __shfl_xor_sync(0xffffffffu, s, 16);
            const float rs2 = rin_s[spm] / s;   // fold rin into the softmax scale
#pragma unroll
            for (int i = 0; i < 4; i++) {
                v[i].x *= rs2; v[i].y *= rs2; v[i].z *= rs2; v[i].w *= rs2;
                *(float4*)((float*)lrow + 4 * i) = v[i];
            }
        }
        __syncthreads();

        // ---- a_sum (t<64, k=t): recover plain soft via *nrm[sp]; coalesced rows ----
        if (t < K_) {
            float s = 0.0f;
#pragma unroll 8
            for (int sp = 0; sp < SP; sp++)
                s += lg[sp * P_LG + t] * nrm_s[sp];
            asum_r += s;
        }

        // ---- GEMM2: vacc[k][c] += (soft*rin)[sp][k] * xraw[sp][c] ----
#pragma unroll 4
        for (int sp = 0; sp < SP; sp++) {
            float4 sv4 = *(const float4*)(lg + sp * P_LG + 4 * tk);
            ull s0 = pk2(sv4.x, sv4.x);
            ull s1 = pk2(sv4.y, sv4.y);
            ull s2 = pk2(sv4.z, sv4.z);
            ull s3 = pk2(sv4.w, sv4.w);
            ulonglong2 xa = *(const ulonglong2*)(xcol2 + sp * P_XT);
            ulonglong2 xb = *(const ulonglong2*)(xcol2 + sp * P_XT + 64);
            vacc[0][0] = fma2(s0, xa.x, vacc[0][0]);
            vacc[0][1] = fma2(s0, xa.y, vacc[0][1]);
            vacc[0][2] = fma2(s0, xb.x, vacc[0][2]);
            vacc[0][3] = fma2(s0, xb.y, vacc[0][3]);
            vacc[1][0] = fma2(s1, xa.x, vacc[1][0]);
            vacc[1][1] = fma2(s1, xa.y, vacc[1][1]);
            vacc[1][2] = fma2(s1, xb.x, vacc[1][2]);
            vacc[1][3] = fma2(s1, xb.y, vacc[1][3]);
            vacc[2][0] = fma2(s2, xa.x, vacc[2][0]);
            vacc[2][1] = fma2(s2, xa.y, vacc[2][1]);
            vacc[2][2] = fma2(s2, xb.x, vacc[2][2]);
            vacc[2][3] = fma2(s2, xb.y, vacc[2][3]);
            vacc[3][0] = fma2(s3, xa.x, vacc[3][0]);
            vacc[3][1] = fma2(s3, xa.y, vacc[3][1]);
            vacc[3][2] = fma2(s3, xb.x, vacc[3][2]);
            vacc[3][3] = fma2(s3, xb.y, vacc[3][3]);
        }
    }

    // ---- deterministic per-block partial writes (128-bit) ----
    float* vb = g_part + (size_t)blockIdx.x * (K_ * C_);
#pragma unroll
    for (int i = 0; i < 4; i++) {
        float2 a = upk2(vacc[i][0]);
        float2 b = upk2(vacc[i][1]);
        *(float4*)(vb + (4 * tk + i) * C_ + 4 * ts) = make_float4(a.x, a.y, b.x, b.y);
        float2 c = upk2(vacc[i][2]);
        float2 d = upk2(vacc[i][3]);
        *(float4*)(vb + (4 * tk + i) * C_ + 64 + 4 * ts) = make_float4(c.x, c.y, d.x, d.y);
    }
    if (t < K_) g_apart[blockIdx.x * K_ + t] = asum_r;
}

// F1: one block per (k, n): reduce chunk partials, subtract a_sum*centroid,
// intra-normalize the row, stash normalized row + its ssq.
__global__ __launch_bounds__(128)
void netvlad_reduce_kernel(const float* __restrict__ centroids)
{
    __shared__ float asv[CHUNKS];
    __shared__ float wred[4];

    const int k = blockIdx.x;
    const int n = blockIdx.y;
    const int c = threadIdx.x;

    if (c < CHUNKS) asv[c] = g_apart[(n * CHUNKS + c) * K_ + k];
    __syncthreads();
    float a = 0.0f;
#pragma unroll
    for (int ch = 0; ch < CHUNKS; ch++) a += asv[ch];

    float s = 0.0f;
#pragma unroll 4
    for (int ch = 0; ch < CHUNKS; ch++)
        s += g_part[(size_t)(n * CHUNKS + ch) * (K_ * C_) + k * C_ + c];

    float val = s - a * centroids[k * C_ + c];

    float ss = val * val;
#pragma unroll
    for (int off = 16; off; off >>= 1) ss += __shfl_xor_sync(0xffffffffu, ss, off);
    if ((c & 31) == 0) wred[c >> 5] = ss;
    __syncthreads();
    float tot = wred[0] + wred[1] + wred[2] + wred[3];
    float rn = 1.0f / fmaxf(sqrtf(tot), 1e-12f);

    g_part[(size_t)(n * CHUNKS) * (K_ * C_) + k * C_ + c] = val * rn;
    if (c == 0) g_apart[(n * CHUNKS) * K_ + k] = tot * rn * rn;
}

// F2: per n, global L2 normalize
__global__ __launch_bounds__(256)
void netvlad_final_kernel(float* __restrict__ out)
{
    __shared__ float kss[K_];
    __shared__ float rs_sh;

    const int n = blockIdx.x;
    const int t = threadIdx.x;

    if (t < K_) kss[t] = g_apart[(n * CHUNKS) * K_ + t];
    __syncthreads();
    if (t == 0) {
        float tot = 0.0f;
#pragma unroll
        for (int k = 0; k < K_; k++) tot += kss[k];
        rs_sh = 1.0f / fmaxf(sqrtf(tot), 1e-12f);
    }
    __syncthreads();
    const float rsc = rs_sh;

    const float* src = g_part + (size_t)(n * CHUNKS) * (K_ * C_);
#pragma unroll 4
    for (int i = t; i < K_ * C_; i += 256)
        out[(size_t)n * K_ * C_ + i] = src[i] * rsc;
}

extern "C" void kernel_launch(void* const* d_in, const int* in_sizes, int n_in,
                              void* d_out, int out_size)
{
    const float* x    = (const float*)d_in[0];
    const float* fc_w = (const float*)d_in[1];
    const float* fc_b = (const float*)d_in[2];
    const float* cent = (const float*)d_in[3];
    float* out = (float*)d_out;

    cudaFuncSetAttribute(netvlad_main_kernel,
                         cudaFuncAttributeMaxDynamicSharedMemorySize,
                         (int)MAIN_SMEM_BYTES);

    netvlad_main_kernel<<<NBLOCKS, THREADS, MAIN_SMEM_BYTES>>>(x, fc_w, fc_b);
    netvlad_reduce_kernel<<<dim3(K_, N_), 128>>>(cent);
    netvlad_final_kernel<<<N_, 256>>>(out);
}